// round 1
// baseline (speedup 1.0000x reference)
#include <cuda_runtime.h>
#include <math.h>

// Problem shape (fixed by the dataset)
#define BB 4
#define TT 2048
#define HH 2048
#define MM (BB * TT)          // 8192 rows
#define NTOT (MM * HH)        // 16,777,216 elements per activation tensor

// Static scratch (allocation-free rule: __device__ globals)
__device__ float gA0[NTOT];   // mixed key   -> later reused as wkv output
__device__ float gA1[NTOT];   // mixed value -> later reused as gated output
__device__ float gA2[NTOT];   // mixed receptance
__device__ float gK[NTOT];    // k = key @ Wk
__device__ float gV[NTOT];    // v = value @ Wv
__device__ float gR[NTOT];    // r_lin = rec @ Wr

// ---------------------------------------------------------------------------
// 1) time-shift + mix: key/value/rec = h*mix + shifted*(1-mix)
// ---------------------------------------------------------------------------
__global__ __launch_bounds__(256) void mix_kernel(
    const float* __restrict__ hidden,
    const float* __restrict__ mixk,
    const float* __restrict__ mixv,
    const float* __restrict__ mixr,
    float* __restrict__ outK,
    float* __restrict__ outV,
    float* __restrict__ outR)
{
    size_t gid = (size_t)blockIdx.x * blockDim.x + threadIdx.x;
    if (gid >= (size_t)NTOT) return;
    int h = (int)(gid % HH);
    size_t bt = gid / HH;
    int t = (int)(bt % TT);

    float hd = hidden[gid];
    float sh = (t > 0) ? hidden[gid - HH] : 0.0f;

    float a = mixk[h];
    outK[gid] = hd * a + sh * (1.0f - a);
    float b = mixv[h];
    outV[gid] = hd * b + sh * (1.0f - b);
    float c = mixr[h];
    outR[gid] = hd * c + sh * (1.0f - c);
}

// ---------------------------------------------------------------------------
// 2) fp32 SIMT GEMM: C[M,N] = A[M,K] * B[K,N], all row-major.
//    128x128 block tile, BK=16, 256 threads, 8x8 per-thread micro-tile.
//    M=8192, N=K=2048, all divisible by tile dims -> no bounds checks.
// ---------------------------------------------------------------------------
#define GBM 128
#define GBN 128
#define GBK 16
#define GTM 8
#define GTN 8

__global__ __launch_bounds__(256) void gemm_f32(
    const float* __restrict__ A,
    const float* __restrict__ B,
    float* __restrict__ C,
    int M, int N, int K)
{
    __shared__ float As[GBK][GBM + 4];
    __shared__ float Bs[GBK][GBN + 4];

    const int bx = blockIdx.x;   // N tile
    const int by = blockIdx.y;   // M tile
    const int tid = threadIdx.x;
    const int tx = tid & 15;     // 0..15
    const int ty = tid >> 4;     // 0..15

    const float* Aptr = A + (size_t)by * GBM * K;
    const float* Bptr = B + (size_t)bx * GBN;

    float acc[GTM][GTN];
#pragma unroll
    for (int i = 0; i < GTM; i++)
#pragma unroll
        for (int j = 0; j < GTN; j++) acc[i][j] = 0.0f;

    for (int k0 = 0; k0 < K; k0 += GBK) {
        // Load A tile (GBM x GBK) -> As transposed [k][m]. 512 float4 total.
#pragma unroll
        for (int i = 0; i < 2; i++) {
            int f = tid + i * 256;          // 0..511
            int row = f >> 2;               // 0..127 (4 float4 per row of 16)
            int c4  = (f & 3) << 2;         // 0,4,8,12
            float4 v = *reinterpret_cast<const float4*>(
                Aptr + (size_t)row * K + (k0 + c4));
            As[c4 + 0][row] = v.x;
            As[c4 + 1][row] = v.y;
            As[c4 + 2][row] = v.z;
            As[c4 + 3][row] = v.w;
        }
        // Load B tile (GBK x GBN). 16 rows x 32 float4/row = 512 float4.
#pragma unroll
        for (int i = 0; i < 2; i++) {
            int f = tid + i * 256;
            int row = f >> 5;               // 0..15
            int c4  = (f & 31) << 2;        // 0..124
            float4 v = *reinterpret_cast<const float4*>(
                Bptr + (size_t)(k0 + row) * N + c4);
            // row stride = 132 floats = 528 B (16B aligned) -> float4 store ok
            *reinterpret_cast<float4*>(&Bs[row][c4]) = v;
        }
        __syncthreads();

#pragma unroll
        for (int kk = 0; kk < GBK; kk++) {
            float a[GTM], b[GTN];
#pragma unroll
            for (int i = 0; i < GTM; i++) a[i] = As[kk][ty * GTM + i];
#pragma unroll
            for (int j = 0; j < GTN; j++) b[j] = Bs[kk][tx * GTN + j];
#pragma unroll
            for (int i = 0; i < GTM; i++)
#pragma unroll
                for (int j = 0; j < GTN; j++)
                    acc[i][j] = fmaf(a[i], b[j], acc[i][j]);
        }
        __syncthreads();
    }

    float* Cp = C + ((size_t)by * GBM + ty * GTM) * N + (size_t)bx * GBN + tx * GTN;
#pragma unroll
    for (int i = 0; i < GTM; i++) {
#pragma unroll
        for (int j = 0; j < GTN; j += 4) {
            float4 v = make_float4(acc[i][j], acc[i][j + 1], acc[i][j + 2], acc[i][j + 3]);
            *reinterpret_cast<float4*>(Cp + (size_t)i * N + j) = v;
        }
    }
}

// ---------------------------------------------------------------------------
// 3) WKV recurrence. One thread per (b, d) channel, sequential over T.
//    Log-sum-exp stabilized exactly as the reference.
// ---------------------------------------------------------------------------
__global__ __launch_bounds__(64) void wkv_kernel(
    const float* __restrict__ time_decay,
    const float* __restrict__ time_first,
    const float* __restrict__ k,
    const float* __restrict__ v,
    float* __restrict__ out)
{
    int gid = blockIdx.x * blockDim.x + threadIdx.x;   // 0..BB*HH-1
    if (gid >= BB * HH) return;
    int d = gid % HH;
    int b = gid / HH;

    const float td = -expf(time_decay[d]);
    const float tf = time_first[d];

    float num = 0.0f, den = 0.0f, mx = -1e38f;

    const size_t base = (size_t)b * TT * HH + d;
    const float* kp = k + base;
    const float* vp = v + base;
    float* op = out + base;

    for (int t = 0; t < TT; t++) {
        const size_t off = (size_t)t * HH;
        float kt = kp[off];
        float vt = vp[off];

        // output
        float ktf = kt + tf;
        float mfo = fmaxf(mx, ktf);
        float e1 = expf(mx - mfo);
        float e2 = expf(ktf - mfo);
        op[off] = (e1 * num + e2 * vt) / (e1 * den + e2);

        // state update with decay
        float mxd = mx + td;
        float mfs = fmaxf(mxd, kt);
        float e1s = expf(mxd - mfs);
        float e2s = expf(kt - mfs);
        num = e1s * num + e2s * vt;
        den = e1s * den + e2s;
        mx = mfs;
    }
}

// ---------------------------------------------------------------------------
// 4) gate: g = sigmoid(r_lin) * rwkv
// ---------------------------------------------------------------------------
__global__ __launch_bounds__(256) void gate_kernel(
    const float* __restrict__ rlin,
    const float* __restrict__ rwkv,
    float* __restrict__ g)
{
    size_t gid = (size_t)blockIdx.x * blockDim.x + threadIdx.x;
    if (gid >= (size_t)NTOT) return;
    float r = rlin[gid];
    float s = 1.0f / (1.0f + expf(-r));
    g[gid] = s * rwkv[gid];
}

// ---------------------------------------------------------------------------
// launch
// ---------------------------------------------------------------------------
extern "C" void kernel_launch(void* const* d_in, const int* in_sizes, int n_in,
                              void* d_out, int out_size)
{
    const float* hidden = (const float*)d_in[0];
    const float* time_decay = (const float*)d_in[1];
    const float* time_first = (const float*)d_in[2];
    const float* mixk = (const float*)d_in[3];
    const float* mixv = (const float*)d_in[4];
    const float* mixr = (const float*)d_in[5];
    const float* Wk = (const float*)d_in[6];
    const float* Wv = (const float*)d_in[7];
    const float* Wr = (const float*)d_in[8];
    const float* Wo = (const float*)d_in[9];
    float* out = (float*)d_out;

    float *pA0, *pA1, *pA2, *pK, *pV, *pR;
    cudaGetSymbolAddress((void**)&pA0, gA0);
    cudaGetSymbolAddress((void**)&pA1, gA1);
    cudaGetSymbolAddress((void**)&pA2, gA2);
    cudaGetSymbolAddress((void**)&pK, gK);
    cudaGetSymbolAddress((void**)&pV, gV);
    cudaGetSymbolAddress((void**)&pR, gR);

    // 1) mix
    {
        int threads = 256;
        int blocks = (NTOT + threads - 1) / threads;
        mix_kernel<<<blocks, threads>>>(hidden, mixk, mixv, mixr, pA0, pA1, pA2);
    }

    // 2) three input GEMMs
    dim3 ggrid(HH / GBN, MM / GBM);   // (16, 64)
    gemm_f32<<<ggrid, 256>>>(pA0, Wk, pK, MM, HH, HH);
    gemm_f32<<<ggrid, 256>>>(pA1, Wv, pV, MM, HH, HH);
    gemm_f32<<<ggrid, 256>>>(pA2, Wr, pR, MM, HH, HH);

    // 3) WKV recurrence -> reuse gA0
    {
        int threads = 64;
        int blocks = (BB * HH + threads - 1) / threads;  // 128 blocks
        wkv_kernel<<<blocks, threads>>>(time_decay, time_first, pK, pV, pA0);
    }

    // 4) gate -> reuse gA1
    {
        int threads = 256;
        int blocks = (NTOT + threads - 1) / threads;
        gate_kernel<<<blocks, threads>>>(pR, pA0, pA1);
    }

    // 5) output GEMM -> d_out
    gemm_f32<<<ggrid, 256>>>(pA1, Wo, out, MM, HH, HH);
}

// round 3
// speedup vs baseline: 1.8225x; 1.8225x over previous
#include <cuda_runtime.h>
#include <math.h>
#include <stdint.h>

// Problem shape (fixed by the dataset)
#define BB 4
#define TT 2048
#define HH 2048
#define MM (BB * TT)          // 8192 rows
#define NTOT (MM * HH)        // 16,777,216 elements per activation tensor

// Static scratch (allocation-free rule: __device__ globals)
__device__ float gA0[NTOT];   // mixed key   -> later reused as wkv output
__device__ float gA1[NTOT];   // mixed value -> later reused as gated output
__device__ float gA2[NTOT];   // mixed receptance
__device__ float gK[NTOT];    // k = key @ Wk
__device__ float gV[NTOT];    // v = value @ Wv
__device__ float gR[NTOT];    // r_lin = rec @ Wr

// ---------------------------------------------------------------------------
// helpers
// ---------------------------------------------------------------------------
__device__ __forceinline__ uint32_t smem_u32(const void* p) {
    return (uint32_t)__cvta_generic_to_shared(p);
}
__device__ __forceinline__ void cp16(uint32_t dst, const void* src) {
    asm volatile("cp.async.ca.shared.global [%0], [%1], 16;" :: "r"(dst), "l"(src));
}
__device__ __forceinline__ uint32_t f2tf32(float x) {
    uint32_t r;
    asm("cvt.rna.tf32.f32 %0, %1;" : "=r"(r) : "f"(x));
    return r;
}

#define MMA_TF32(c, a0, a1, a2, a3, b0, b1)                                   \
    asm volatile(                                                             \
        "mma.sync.aligned.m16n8k8.row.col.f32.tf32.tf32.f32 "                 \
        "{%0,%1,%2,%3},{%4,%5,%6,%7},{%8,%9},{%0,%1,%2,%3};"                  \
        : "+f"(c[0]), "+f"(c[1]), "+f"(c[2]), "+f"(c[3])                      \
        : "r"(a0), "r"(a1), "r"(a2), "r"(a3), "r"(b0), "r"(b1))

// ---------------------------------------------------------------------------
// 1) time-shift + mix
// ---------------------------------------------------------------------------
__global__ __launch_bounds__(256) void mix_kernel(
    const float* __restrict__ hidden,
    const float* __restrict__ mixk,
    const float* __restrict__ mixv,
    const float* __restrict__ mixr,
    float* __restrict__ outK,
    float* __restrict__ outV,
    float* __restrict__ outR)
{
    size_t gid = (size_t)blockIdx.x * blockDim.x + threadIdx.x;
    if (gid >= (size_t)NTOT) return;
    int h = (int)(gid % HH);
    size_t bt = gid / HH;
    int t = (int)(bt % TT);

    float hd = hidden[gid];
    float sh = (t > 0) ? hidden[gid - HH] : 0.0f;

    float a = mixk[h];
    outK[gid] = hd * a + sh * (1.0f - a);
    float b = mixv[h];
    outV[gid] = hd * b + sh * (1.0f - b);
    float c = mixr[h];
    outR[gid] = hd * c + sh * (1.0f - c);
}

// ---------------------------------------------------------------------------
// 2) TF32 tensor-core GEMM with 3xTF32 compensation.
//    C[M,N] = A[M,K] * B[K,N], row-major. M=8192, N=K=2048.
//    CTA tile 128x128, BK=16, 256 threads (8 warps, 2x4), warp tile 64x32,
//    mma.m16n8k8, cp.async double-buffered SMEM.
// ---------------------------------------------------------------------------
#define BM 128
#define BN 128
#define BKg 16
#define AST 20     // A smem row stride (floats): bank-conflict-free for frag loads
#define BST 136    // B smem row stride (floats)

__global__ __launch_bounds__(256, 1) void gemm_tf32(
    const float* __restrict__ A,
    const float* __restrict__ B,
    float* __restrict__ C,
    int M, int N, int K)
{
    __shared__ float As[2][BM][AST];    // 20.0 KB
    __shared__ float Bs[2][BKg][BST];   // 17.0 KB

    const int bx = blockIdx.x;     // N tile
    const int by = blockIdx.y;     // M tile
    const int tid = threadIdx.x;
    const int wid = tid >> 5;
    const int lane = tid & 31;
    const int g = lane >> 2;       // groupID 0..7
    const int tig = lane & 3;      // thread-in-group 0..3
    const int wm = (wid >> 2) * 64;  // warp m offset: 0 or 64
    const int wn = (wid & 3) * 32;   // warp n offset: 0,32,64,96

    const float* Ab = A + (size_t)by * BM * K;
    const float* Bb = B + (size_t)bx * BN;

    // global->smem load indices
    const int arow = tid >> 2;          // 0..63
    const int ac4  = (tid & 3) * 4;     // 0,4,8,12
    const int brow = tid >> 5;          // 0..7
    const int bc4  = (tid & 31) * 4;    // 0..124

    float acc[4][4][4];
#pragma unroll
    for (int i = 0; i < 4; i++)
#pragma unroll
        for (int j = 0; j < 4; j++)
#pragma unroll
            for (int e = 0; e < 4; e++) acc[i][j][e] = 0.0f;

    const int nk = K / BKg;   // 128

    // ---- prologue: load tile 0 into buffer 0
    {
        cp16(smem_u32(&As[0][arow][ac4]),      Ab + (size_t)arow * K + ac4);
        cp16(smem_u32(&As[0][arow + 64][ac4]), Ab + (size_t)(arow + 64) * K + ac4);
        cp16(smem_u32(&Bs[0][brow][bc4]),      Bb + (size_t)brow * N + bc4);
        cp16(smem_u32(&Bs[0][brow + 8][bc4]),  Bb + (size_t)(brow + 8) * N + bc4);
        asm volatile("cp.async.commit_group;");
    }

    for (int i = 0; i < nk; i++) {
        const int cur = i & 1;
        if (i + 1 < nk) {
            const int nb = cur ^ 1;
            const int k0 = (i + 1) * BKg;
            cp16(smem_u32(&As[nb][arow][ac4]),      Ab + (size_t)arow * K + k0 + ac4);
            cp16(smem_u32(&As[nb][arow + 64][ac4]), Ab + (size_t)(arow + 64) * K + k0 + ac4);
            cp16(smem_u32(&Bs[nb][brow][bc4]),      Bb + (size_t)(k0 + brow) * N + bc4);
            cp16(smem_u32(&Bs[nb][brow + 8][bc4]),  Bb + (size_t)(k0 + brow + 8) * N + bc4);
        }
        asm volatile("cp.async.commit_group;");
        asm volatile("cp.async.wait_group 1;");
        __syncthreads();

        // ---- compute from buffer `cur`: 2 k-steps of 8
#pragma unroll
        for (int ks = 0; ks < BKg; ks += 8) {
            uint32_t aHi[4][4], aLo[4][4];
            uint32_t bHi[4][2], bLo[4][2];
#pragma unroll
            for (int mt = 0; mt < 4; mt++) {
                const int r0 = wm + mt * 16 + g;
                float a0 = As[cur][r0][ks + tig];
                float a1 = As[cur][r0 + 8][ks + tig];
                float a2 = As[cur][r0][ks + tig + 4];
                float a3 = As[cur][r0 + 8][ks + tig + 4];
                aHi[mt][0] = f2tf32(a0); aLo[mt][0] = f2tf32(a0 - __uint_as_float(aHi[mt][0]));
                aHi[mt][1] = f2tf32(a1); aLo[mt][1] = f2tf32(a1 - __uint_as_float(aHi[mt][1]));
                aHi[mt][2] = f2tf32(a2); aLo[mt][2] = f2tf32(a2 - __uint_as_float(aHi[mt][2]));
                aHi[mt][3] = f2tf32(a3); aLo[mt][3] = f2tf32(a3 - __uint_as_float(aHi[mt][3]));
            }
#pragma unroll
            for (int nt = 0; nt < 4; nt++) {
                const int col = wn + nt * 8 + g;
                float b0 = Bs[cur][ks + tig][col];
                float b1 = Bs[cur][ks + tig + 4][col];
                bHi[nt][0] = f2tf32(b0); bLo[nt][0] = f2tf32(b0 - __uint_as_float(bHi[nt][0]));
                bHi[nt][1] = f2tf32(b1); bLo[nt][1] = f2tf32(b1 - __uint_as_float(bHi[nt][1]));
            }
#pragma unroll
            for (int mt = 0; mt < 4; mt++) {
#pragma unroll
                for (int nt = 0; nt < 4; nt++) {
                    MMA_TF32(acc[mt][nt], aHi[mt][0], aHi[mt][1], aHi[mt][2], aHi[mt][3],
                             bHi[nt][0], bHi[nt][1]);
                    MMA_TF32(acc[mt][nt], aLo[mt][0], aLo[mt][1], aLo[mt][2], aLo[mt][3],
                             bHi[nt][0], bHi[nt][1]);
                    MMA_TF32(acc[mt][nt], aHi[mt][0], aHi[mt][1], aHi[mt][2], aHi[mt][3],
                             bLo[nt][0], bLo[nt][1]);
                }
            }
        }
        __syncthreads();
    }

    // ---- epilogue
#pragma unroll
    for (int mt = 0; mt < 4; mt++) {
#pragma unroll
        for (int nt = 0; nt < 4; nt++) {
            const size_t row0 = (size_t)by * BM + wm + mt * 16 + g;
            const size_t col  = (size_t)bx * BN + wn + nt * 8 + 2 * tig;
            float2 v0 = make_float2(acc[mt][nt][0], acc[mt][nt][1]);
            float2 v1 = make_float2(acc[mt][nt][2], acc[mt][nt][3]);
            *reinterpret_cast<float2*>(C + row0 * N + col) = v0;
            *reinterpret_cast<float2*>(C + (row0 + 8) * N + col) = v1;
        }
    }
}

// ---------------------------------------------------------------------------
// 3) WKV recurrence. One thread per (b, d) channel, sequential over T.
// ---------------------------------------------------------------------------
__global__ __launch_bounds__(128) void wkv_kernel(
    const float* __restrict__ time_decay,
    const float* __restrict__ time_first,
    const float* __restrict__ k,
    const float* __restrict__ v,
    float* __restrict__ out)
{
    int gid = blockIdx.x * blockDim.x + threadIdx.x;   // 0..BB*HH-1
    if (gid >= BB * HH) return;
    int d = gid % HH;
    int b = gid / HH;

    const float td = -expf(time_decay[d]);
    const float tf = time_first[d];

    float num = 0.0f, den = 0.0f, mx = -1e38f;

    const size_t base = (size_t)b * TT * HH + d;
    const float* kp = k + base;
    const float* vp = v + base;
    float* op = out + base;

    for (int t = 0; t < TT; t++) {
        const size_t off = (size_t)t * HH;
        float kt = kp[off];
        float vt = vp[off];

        float ktf = kt + tf;
        float mfo = fmaxf(mx, ktf);
        float e1 = expf(mx - mfo);
        float e2 = expf(ktf - mfo);
        op[off] = (e1 * num + e2 * vt) / (e1 * den + e2);

        float mxd = mx + td;
        float mfs = fmaxf(mxd, kt);
        float e1s = expf(mxd - mfs);
        float e2s = expf(kt - mfs);
        num = e1s * num + e2s * vt;
        den = e1s * den + e2s;
        mx = mfs;
    }
}

// ---------------------------------------------------------------------------
// 4) gate: g = sigmoid(r_lin) * rwkv
// ---------------------------------------------------------------------------
__global__ __launch_bounds__(256) void gate_kernel(
    const float* __restrict__ rlin,
    const float* __restrict__ rwkv,
    float* __restrict__ g)
{
    size_t gid = (size_t)blockIdx.x * blockDim.x + threadIdx.x;
    if (gid >= (size_t)NTOT) return;
    float r = rlin[gid];
    float s = 1.0f / (1.0f + expf(-r));
    g[gid] = s * rwkv[gid];
}

// ---------------------------------------------------------------------------
// launch
// ---------------------------------------------------------------------------
extern "C" void kernel_launch(void* const* d_in, const int* in_sizes, int n_in,
                              void* d_out, int out_size)
{
    const float* hidden = (const float*)d_in[0];
    const float* time_decay = (const float*)d_in[1];
    const float* time_first = (const float*)d_in[2];
    const float* mixk = (const float*)d_in[3];
    const float* mixv = (const float*)d_in[4];
    const float* mixr = (const float*)d_in[5];
    const float* Wk = (const float*)d_in[6];
    const float* Wv = (const float*)d_in[7];
    const float* Wr = (const float*)d_in[8];
    const float* Wo = (const float*)d_in[9];
    float* out = (float*)d_out;

    float *pA0, *pA1, *pA2, *pK, *pV, *pR;
    cudaGetSymbolAddress((void**)&pA0, gA0);
    cudaGetSymbolAddress((void**)&pA1, gA1);
    cudaGetSymbolAddress((void**)&pA2, gA2);
    cudaGetSymbolAddress((void**)&pK, gK);
    cudaGetSymbolAddress((void**)&pV, gV);
    cudaGetSymbolAddress((void**)&pR, gR);

    // 1) mix
    {
        int threads = 256;
        int blocks = (NTOT + threads - 1) / threads;
        mix_kernel<<<blocks, threads>>>(hidden, mixk, mixv, mixr, pA0, pA1, pA2);
    }

    // 2) three input GEMMs
    dim3 ggrid(HH / BN, MM / BM);   // (16, 64)
    gemm_tf32<<<ggrid, 256>>>(pA0, Wk, pK, MM, HH, HH);
    gemm_tf32<<<ggrid, 256>>>(pA1, Wv, pV, MM, HH, HH);
    gemm_tf32<<<ggrid, 256>>>(pA2, Wr, pR, MM, HH, HH);

    // 3) WKV recurrence -> reuse gA0
    {
        int threads = 128;
        int blocks = (BB * HH + threads - 1) / threads;  // 64 blocks
        wkv_kernel<<<blocks, threads>>>(time_decay, time_first, pK, pV, pA0);
    }

    // 4) gate -> reuse gA1
    {
        int threads = 256;
        int blocks = (NTOT + threads - 1) / threads;
        gate_kernel<<<blocks, threads>>>(pR, pA0, pA1);
    }

    // 5) output GEMM -> d_out
    gemm_tf32<<<ggrid, 256>>>(pA1, Wo, out, MM, HH, HH);
}